// round 12
// baseline (speedup 1.0000x reference)
#include <cuda_runtime.h>
#include <cuda.h>
#include <cstdint>

#define BB     16
#define CC     3
#define HH     512
#define WW     512
#define NH     63
#define NW     63
#define NN     (NH * NW)          // 3969
#define FDIM   768
#define KNB    8
#define F4PER  192

#define TPB    512

// tile = 2x8 patches; stripe = 3ch x 24 x 72 floats = 20736 B
#define TI     2
#define TJ     8
#define ITILES 32                 // i0 = it*2, patches i in [0,63] (63 guarded)
#define JTILES 8                  // j0 = jt*8, patches j in [0,63] (63 guarded)
#define TILES  (BB * ITILES * JTILES)   // 4096
#define TILES_PER_CTA 8
#define PATCH_CTAS (TILES / TILES_PER_CTA)  // 512

#define SROWS  24
#define SCOLS  72
#define STRIPE_FLOATS (CC * SROWS * SCOLS)  // 5184
#define STRIPE_BYTES  (STRIPE_FLOATS * 4)   // 20736

#define NBUF   2
#define OFF_BARS (NBUF * STRIPE_BYTES)      // 41472
#define SMEM_DYN (OFF_BARS + NBUF * 8)      // 41488

#define POS_FLOATS   (BB * NN * 2)                  // 127,008
#define EDGE_FLOATS  (BB * 2 * NN * KNB)            // 1,016,064
#define EXTRA_FLOATS (POS_FLOATS + EDGE_FLOATS)     // 1,143,072
#define EXTRA_BLOCKS ((EXTRA_FLOATS + TPB - 1) / TPB)   // 2,233

#define CX(a, b) { int _lo = min(a, b); b = max(a, b); a = _lo; }

__device__ __forceinline__ uint32_t smem_u32(const void* p) {
    uint32_t a;
    asm("{ .reg .u64 t; cvta.to.shared.u64 t, %1; cvt.u32.u64 %0, t; }"
        : "=r"(a) : "l"(p));
    return a;
}

// ---------------------------------------------------------------------------
// 512-thread persistent movers (16 warps = 16 patches/tile, 1 patch/warp):
//  blocks [0, PATCH_CTAS): 8 tiles (2x8 patches) each, double-buffered TMA
//    stripe loads issued 2 ahead; emit = LDS.128 (2-way max) -> STG.128
//    streaming stores. 4 CTAs/SM -> 2048 threads (full thread occupancy).
//  blocks [PATCH_CTAS, ...): positions + edge_index (register kNN via sorted
//    insertion network; key = d2*4096+idx reproduces top_k(-d2)'s
//    (d2 asc, idx asc) ordering).
// ---------------------------------------------------------------------------
__global__ void __launch_bounds__(TPB)
fused_kernel(const __grid_constant__ CUtensorMap tmap,
             float* __restrict__ out)
{
    extern __shared__ __align__(128) unsigned char smem[];

    int bid = blockIdx.x;

    if (bid >= PATCH_CTAS) {
        int e = (bid - PATCH_CTAS) * TPB + threadIdx.x;
        if (e >= EXTRA_FLOATS) return;

        const long long P0 = (long long)BB * NN * FDIM;

        if (e < POS_FLOATS) {
            int n = (e >> 1) % NN;
            out[P0 + e] = (float)((e & 1) ? (n % NW) : (n / NW));
            return;
        }

        int e2 = e - POS_FLOATS;
        int r  = e2 % (2 * NN * KNB);
        float v;
        if (r < NN * KNB) {
            v = (float)(r >> 3);                    // src row: node id
        } else {
            int q = r - NN * KNB;
            int n = q >> 3;
            int m = q & 7;
            int i = n / NW;
            int j = n % NW;

            int t0 = 0x7fffffff, t1 = 0x7fffffff, t2 = 0x7fffffff, t3 = 0x7fffffff;
            int t4 = 0x7fffffff, t5 = 0x7fffffff, t6 = 0x7fffffff, t7 = 0x7fffffff;
            #pragma unroll
            for (int di = -2; di <= 2; di++) {
                #pragma unroll
                for (int dj = -2; dj <= 2; dj++) {
                    if (di == 0 && dj == 0) continue;
                    int ii = i + di;
                    int jj = j + dj;
                    bool ok = (ii >= 0) & (ii < NH) & (jj >= 0) & (jj < NW);
                    int key = ok ? ((di*di + dj*dj) * 4096 + (ii * NW + jj))
                                 : 0x7fffffff;
                    int t8 = key;
                    CX(t7, t8); CX(t6, t7); CX(t5, t6); CX(t4, t5);
                    CX(t3, t4); CX(t2, t3); CX(t1, t2); CX(t0, t1);
                }
            }
            int a0 = (m & 1) ? t1 : t0;
            int a1 = (m & 1) ? t3 : t2;
            int a2 = (m & 1) ? t5 : t4;
            int a3 = (m & 1) ? t7 : t6;
            int b0 = (m & 2) ? a1 : a0;
            int b1 = (m & 2) ? a3 : a2;
            int sel = (m & 4) ? b1 : b0;
            v = (float)(sel & 4095);
        }
        out[P0 + POS_FLOATS + e2] = v;
        return;
    }

    // ---- persistent patch mover ----
    uint32_t sbase = smem_u32(smem);
    uint32_t mb    = sbase + OFF_BARS;

    if (threadIdx.x == 0) {
        asm volatile("mbarrier.init.shared.b64 [%0], 1;" :: "r"(mb)     : "memory");
        asm volatile("mbarrier.init.shared.b64 [%0], 1;" :: "r"(mb + 8) : "memory");
        asm volatile("fence.proxy.async.shared::cta;" ::: "memory");
    }
    __syncthreads();

    int tile0 = bid * TILES_PER_CTA;

    auto issue_load = [&](int q) {   // thread 0 only
        int tile = tile0 + q;
        int b  = tile >> 8;             // / 256
        int rr = tile & 255;
        int it = rr >> 3;               // 0..31
        int jt = rr & 7;                // 0..7
        int slot = q & 1;
        uint32_t bar = mb + slot * 8;
        uint32_t dst = sbase + slot * STRIPE_BYTES;
        asm volatile("mbarrier.arrive.expect_tx.shared.b64 _, [%0], %1;"
                     :: "r"(bar), "r"((uint32_t)STRIPE_BYTES) : "memory");
        asm volatile(
            "cp.async.bulk.tensor.3d.shared::cta.global.tile.mbarrier::complete_tx::bytes "
            "[%0], [%1, {%2, %3, %4}], [%5];"
            :: "r"(dst), "l"(&tmap),
               "r"(jt * 64), "r"(it * 16), "r"(b * CC), "r"(bar)
            : "memory");
    };

    if (threadIdx.x == 0) { issue_load(0); issue_load(1); }

    int w    = threadIdx.x >> 5;        // warp -> patch (16 patches/tile)
    int lane = threadIdx.x & 31;
    int pi   = w >> 3;                  // 0..1
    int pj   = w & 7;                   // 0..7

    for (int q = 0; q < TILES_PER_CTA; q++) {
        int tile = tile0 + q;
        int b  = tile >> 8;
        int rr = tile & 255;
        int it = rr >> 3;
        int jt = rr & 7;

        int slot = q & 1;
        uint32_t bar = mb + slot * 8;
        uint32_t ph  = (q >> 1) & 1;
        const float* sin = (const float*)(smem + slot * STRIPE_BYTES);

        uint32_t done = 0;
        while (!done) {
            asm volatile(
                "{ .reg .pred p;"
                "  mbarrier.try_wait.parity.acquire.cta.shared::cta.b64 p, [%1], %2, 0x989680;"
                "  selp.b32 %0, 1, 0, p; }"
                : "=r"(done) : "r"(bar), "r"(ph) : "memory");
        }

        // emit: warp w -> patch (pi, pj)
        int i = it * TI + pi;
        int j = jt * TJ + pj;
        if (i < NH && j < NW) {
            float4* dst = reinterpret_cast<float4*>(out) +
                          (long long)(b * NN + i * NW + j) * F4PER;
            #pragma unroll
            for (int itr = 0; itr < 6; itr++) {
                int r4 = itr * 32 + lane;          // 0..191
                int c  = r4 >> 6;
                int u  = (r4 >> 2) & 15;
                int vg = r4 & 3;
                const float4 v = *reinterpret_cast<const float4*>(
                    &sin[(c * SROWS + pi * 8 + u) * SCOLS + pj * 8 + vg * 4]);
                __stcs(dst + r4, v);
            }
        }

        __syncthreads();   // all reads of buf slot done before reuse
        if (threadIdx.x == 0 && q + 2 < TILES_PER_CTA) issue_load(q + 2);
    }
}

// ---------------------------------------------------------------------------
extern "C" void kernel_launch(void* const* d_in, const int* in_sizes, int n_in,
                              void* d_out, int out_size)
{
    const float* x = (const float*)d_in[0];
    float* out = (float*)d_out;

    typedef CUresult (*EncodeFn)(
        CUtensorMap*, CUtensorMapDataType, cuuint32_t, void*,
        const cuuint64_t*, const cuuint64_t*, const cuuint32_t*,
        const cuuint32_t*, CUtensorMapInterleave, CUtensorMapSwizzle,
        CUtensorMapL2promotion, CUtensorMapFloatOOBfill);
    EncodeFn encode = nullptr;
    cudaGetDriverEntryPoint("cuTensorMapEncodeTiled", (void**)&encode,
                            cudaEnableDefault, nullptr);

    CUtensorMap tmap;
    cuuint64_t dims[3]    = {WW, HH, (cuuint64_t)(BB * CC)};
    cuuint64_t strides[2] = {WW * sizeof(float),
                             (cuuint64_t)HH * WW * sizeof(float)};
    cuuint32_t box[3]     = {SCOLS, SROWS, CC};   // 72 x 24 x 3 floats
    cuuint32_t estr[3]    = {1, 1, 1};
    encode(&tmap, CU_TENSOR_MAP_DATA_TYPE_FLOAT32, 3, (void*)x,
           dims, strides, box, estr,
           CU_TENSOR_MAP_INTERLEAVE_NONE, CU_TENSOR_MAP_SWIZZLE_NONE,
           CU_TENSOR_MAP_L2_PROMOTION_L2_128B,
           CU_TENSOR_MAP_FLOAT_OOB_FILL_NONE);

    cudaFuncSetAttribute(fused_kernel,
                         cudaFuncAttributeMaxDynamicSharedMemorySize, SMEM_DYN);
    fused_kernel<<<PATCH_CTAS + EXTRA_BLOCKS, TPB, SMEM_DYN>>>(tmap, out);
}

// round 13
// speedup vs baseline: 1.0506x; 1.0506x over previous
#include <cuda_runtime.h>
#include <cuda.h>
#include <cstdint>

#define BB     16
#define CC     3
#define HH     512
#define WW     512
#define NH     63
#define NW     63
#define NN     (NH * NW)          // 3969
#define FDIM   768
#define KNB    8
#define F4PER  192

#define TPB    256

// tile = 2x4 patches; stripe = 3ch x 24 x 40 floats = 11520 B
#define TI     2
#define TJ     4
#define ITILES 32
#define JTILES 16
#define TILES  (BB * ITILES * JTILES)   // 8192
#define TILES_PER_CTA 8
#define PATCH_CTAS (TILES / TILES_PER_CTA)  // 1024

#define SROWS  24
#define SCOLS  40
#define STRIPE_FLOATS (CC * SROWS * SCOLS)  // 2880
#define STRIPE_BYTES  (STRIPE_FLOATS * 4)   // 11520

#define NBUF   2
#define OFF_BARS (NBUF * STRIPE_BYTES)      // 23040
#define SMEM_DYN (OFF_BARS + NBUF * 8)      // 23056

#define POS_FLOATS   (BB * NN * 2)                  // 127,008  (even)
#define EDGE_FLOATS  (BB * 2 * NN * KNB)            // 1,016,064 (even)
#define EXTRA_F2     ((POS_FLOATS + EDGE_FLOATS) / 2)   // 571,536 float2
#define EXTRA_BLOCKS ((EXTRA_F2 + TPB - 1) / TPB)   // 2,233

#define CX(a, b) { int _lo = min(a, b); b = max(a, b); a = _lo; }

__device__ __forceinline__ uint32_t smem_u32(const void* p) {
    uint32_t a;
    asm("{ .reg .u64 t; cvta.to.shared.u64 t, %1; cvt.u32.u64 %0, t; }"
        : "=r"(a) : "l"(p));
    return a;
}

// Neighbor id for node n=(i,j), rank m: register kNN via sorted insertion
// network over the Chebyshev radius-2 window; key = d2*4096+idx reproduces
// top_k(-d2)'s (d2 asc, idx asc) ordering exactly.
__device__ __forceinline__ int knn_idx(int i, int j, int m)
{
    int t0 = 0x7fffffff, t1 = 0x7fffffff, t2 = 0x7fffffff, t3 = 0x7fffffff;
    int t4 = 0x7fffffff, t5 = 0x7fffffff, t6 = 0x7fffffff, t7 = 0x7fffffff;
    #pragma unroll
    for (int di = -2; di <= 2; di++) {
        #pragma unroll
        for (int dj = -2; dj <= 2; dj++) {
            if (di == 0 && dj == 0) continue;
            int ii = i + di;
            int jj = j + dj;
            bool ok = (ii >= 0) & (ii < NH) & (jj >= 0) & (jj < NW);
            int key = ok ? ((di*di + dj*dj) * 4096 + (ii * NW + jj))
                         : 0x7fffffff;
            int t8 = key;
            CX(t7, t8); CX(t6, t7); CX(t5, t6); CX(t4, t5);
            CX(t3, t4); CX(t2, t3); CX(t1, t2); CX(t0, t1);
        }
    }
    int a0 = (m & 1) ? t1 : t0;
    int a1 = (m & 1) ? t3 : t2;
    int a2 = (m & 1) ? t5 : t4;
    int a3 = (m & 1) ? t7 : t6;
    int b0 = (m & 2) ? a1 : a0;
    int b1 = (m & 2) ? a3 : a2;
    int sel = (m & 4) ? b1 : b0;
    return sel & 4095;
}

// ---------------------------------------------------------------------------
// blocks [0, PATCH_CTAS): persistent movers (R11 config): 8 tiles of 2x4
//   patches each, double-buffered TMA stripe loads issued 2 ahead; emit =
//   1 patch/warp, LDS.128 (2-way max) -> STG.128 streaming stores.
// blocks [PATCH_CTAS, ...): positions + edge_index, one float2 per thread.
// ---------------------------------------------------------------------------
__global__ void __launch_bounds__(TPB)
fused_kernel(const __grid_constant__ CUtensorMap tmap,
             float* __restrict__ out)
{
    extern __shared__ __align__(128) unsigned char smem[];

    int bid = blockIdx.x;

    if (bid >= PATCH_CTAS) {
        int e2i = (bid - PATCH_CTAS) * TPB + threadIdx.x;   // float2 index
        if (e2i >= EXTRA_F2) return;

        const long long P0 = (long long)BB * NN * FDIM;     // even
        int e = e2i * 2;                                    // float index
        float2 v;

        if (e < POS_FLOATS) {
            // pair = (i, j) of node n
            int n = (e >> 1) % NN;
            v.x = (float)(n / NW);
            v.y = (float)(n % NW);
        } else {
            int r = (e - POS_FLOATS) % (2 * NN * KNB);      // even
            if (r < NN * KNB) {
                // src row: node ids; pair shares or crosses node boundary
                v.x = (float)(r >> 3);
                v.y = (float)((r + 1) >> 3);
            } else {
                int q = r - NN * KNB;                        // even
                int n = q >> 3;
                int m = q & 7;                               // even, m+1 <= 7
                int i = n / NW;
                int j = n % NW;
                v.x = (float)knn_idx(i, j, m);
                v.y = (float)knn_idx(i, j, m + 1);           // same node (m even)
            }
        }
        reinterpret_cast<float2*>(out + P0)[e2i] = v;
        return;
    }

    // ---- persistent patch mover (R11) ----
    uint32_t sbase = smem_u32(smem);
    uint32_t mb    = sbase + OFF_BARS;

    if (threadIdx.x == 0) {
        asm volatile("mbarrier.init.shared.b64 [%0], 1;" :: "r"(mb)     : "memory");
        asm volatile("mbarrier.init.shared.b64 [%0], 1;" :: "r"(mb + 8) : "memory");
        asm volatile("fence.proxy.async.shared::cta;" ::: "memory");
    }
    __syncthreads();

    int tile0 = bid * TILES_PER_CTA;

    auto issue_load = [&](int q) {   // thread 0 only
        int tile = tile0 + q;
        int b  = tile >> 9;             // / 512
        int rr = tile & 511;
        int it = rr >> 4;               // 0..31
        int jt = rr & 15;               // 0..15
        int slot = q & 1;
        uint32_t bar = mb + slot * 8;
        uint32_t dst = sbase + slot * STRIPE_BYTES;
        asm volatile("mbarrier.arrive.expect_tx.shared.b64 _, [%0], %1;"
                     :: "r"(bar), "r"((uint32_t)STRIPE_BYTES) : "memory");
        asm volatile(
            "cp.async.bulk.tensor.3d.shared::cta.global.tile.mbarrier::complete_tx::bytes "
            "[%0], [%1, {%2, %3, %4}], [%5];"
            :: "r"(dst), "l"(&tmap),
               "r"(jt * 32), "r"(it * 16), "r"(b * CC), "r"(bar)
            : "memory");
    };

    if (threadIdx.x == 0) { issue_load(0); issue_load(1); }

    int w    = threadIdx.x >> 5;        // warp -> patch (8 patches/tile)
    int lane = threadIdx.x & 31;
    int pi   = w >> 2;                  // 0..1
    int pj   = w & 3;                   // 0..3

    for (int q = 0; q < TILES_PER_CTA; q++) {
        int tile = tile0 + q;
        int b  = tile >> 9;
        int rr = tile & 511;
        int it = rr >> 4;
        int jt = rr & 15;

        int slot = q & 1;
        uint32_t bar = mb + slot * 8;
        uint32_t ph  = (q >> 1) & 1;
        const float* sin = (const float*)(smem + slot * STRIPE_BYTES);

        uint32_t done = 0;
        while (!done) {
            asm volatile(
                "{ .reg .pred p;"
                "  mbarrier.try_wait.parity.acquire.cta.shared::cta.b64 p, [%1], %2, 0x989680;"
                "  selp.b32 %0, 1, 0, p; }"
                : "=r"(done) : "r"(bar), "r"(ph) : "memory");
        }

        // emit: warp w -> patch (pi, pj)
        int i = it * TI + pi;
        int j = jt * TJ + pj;
        if (i < NH && j < NW) {
            float4* dst = reinterpret_cast<float4*>(out) +
                          (long long)(b * NN + i * NW + j) * F4PER;
            #pragma unroll
            for (int itr = 0; itr < 6; itr++) {
                int r4 = itr * 32 + lane;          // 0..191
                int c  = r4 >> 6;
                int u  = (r4 >> 2) & 15;
                int vg = r4 & 3;
                const float4 v = *reinterpret_cast<const float4*>(
                    &sin[(c * SROWS + pi * 8 + u) * SCOLS + pj * 8 + vg * 4]);
                __stcs(dst + r4, v);
            }
        }

        __syncthreads();   // all reads of buf slot done before reuse
        if (threadIdx.x == 0 && q + 2 < TILES_PER_CTA) issue_load(q + 2);
    }
}

// ---------------------------------------------------------------------------
extern "C" void kernel_launch(void* const* d_in, const int* in_sizes, int n_in,
                              void* d_out, int out_size)
{
    const float* x = (const float*)d_in[0];
    float* out = (float*)d_out;

    typedef CUresult (*EncodeFn)(
        CUtensorMap*, CUtensorMapDataType, cuuint32_t, void*,
        const cuuint64_t*, const cuuint64_t*, const cuuint32_t*,
        const cuuint32_t*, CUtensorMapInterleave, CUtensorMapSwizzle,
        CUtensorMapL2promotion, CUtensorMapFloatOOBfill);
    EncodeFn encode = nullptr;
    cudaGetDriverEntryPoint("cuTensorMapEncodeTiled", (void**)&encode,
                            cudaEnableDefault, nullptr);

    CUtensorMap tmap;
    cuuint64_t dims[3]    = {WW, HH, (cuuint64_t)(BB * CC)};
    cuuint64_t strides[2] = {WW * sizeof(float),
                             (cuuint64_t)HH * WW * sizeof(float)};
    cuuint32_t box[3]     = {SCOLS, SROWS, CC};   // 40 x 24 x 3 floats
    cuuint32_t estr[3]    = {1, 1, 1};
    encode(&tmap, CU_TENSOR_MAP_DATA_TYPE_FLOAT32, 3, (void*)x,
           dims, strides, box, estr,
           CU_TENSOR_MAP_INTERLEAVE_NONE, CU_TENSOR_MAP_SWIZZLE_NONE,
           CU_TENSOR_MAP_L2_PROMOTION_L2_128B,
           CU_TENSOR_MAP_FLOAT_OOB_FILL_NONE);

    cudaFuncSetAttribute(fused_kernel,
                         cudaFuncAttributeMaxDynamicSharedMemorySize, SMEM_DYN);
    fused_kernel<<<PATCH_CTAS + EXTRA_BLOCKS, TPB, SMEM_DYN>>>(tmap, out);
}